// round 4
// baseline (speedup 1.0000x reference)
#include <cuda_runtime.h>
#include <cuda_bf16.h>
#include <cstdint>

#define N_NODES_MAX 50000
#define E_MAX       800000
#define CH 128

// -------- device scratch --------
__device__ float g_h[(size_t)N_NODES_MAX * CH];   // x @ W
__device__ float g_dinv[N_NODES_MAX];
__device__ int   g_cnt[N_NODES_MAX];
__device__ int   g_rowptr[N_NODES_MAX + 1];
__device__ int   g_cursor[N_NODES_MAX];
__device__ int   g_esrc[E_MAX];

// -------- k1: zero counts --------
__global__ void k_zero(int n) {
    int i = blockIdx.x * blockDim.x + threadIdx.x;
    if (i < n) g_cnt[i] = 0;
}

// -------- k2: histogram over dst --------
__global__ void k_count(const int* __restrict__ dst, int E) {
    int e = blockIdx.x * blockDim.x + threadIdx.x;
    if (e < E) atomicAdd(&g_cnt[dst[e]], 1);
}

// -------- k3: single-block exclusive scan -> rowptr/cursor, plus dinv --------
__global__ void k_scan(int n, int E) {
    __shared__ int tot[1024];
    int t = threadIdx.x;
    int chunk = (n + 1023) / 1024;
    int lo = t * chunk;
    int hi = min(n, lo + chunk);
    int s = 0;
    for (int i = lo; i < hi; i++) s += g_cnt[i];
    tot[t] = s;
    __syncthreads();
    // Hillis-Steele inclusive scan over 1024 totals
    for (int off = 1; off < 1024; off <<= 1) {
        int v = (t >= off) ? tot[t - off] : 0;
        __syncthreads();
        tot[t] += v;
        __syncthreads();
    }
    int run = (t > 0) ? tot[t - 1] : 0;
    for (int i = lo; i < hi; i++) {
        int c = g_cnt[i];
        g_rowptr[i] = run;
        g_cursor[i] = run;
        g_dinv[i] = rsqrtf((float)(c + 1));   // +1 self-loop
        run += c;
    }
    if (t == 0) g_rowptr[n] = E;
}

// -------- k4: bucket edge sources --------
__global__ void k_fill(const int* __restrict__ src, const int* __restrict__ dst, int E) {
    int e = blockIdx.x * blockDim.x + threadIdx.x;
    if (e < E) {
        int pos = atomicAdd(&g_cursor[dst[e]], 1);
        g_esrc[pos] = src[e];
    }
}

// -------- k5: GEMM h = x @ W --------
// 64-row tiles, 256 threads. Thread (ty,tx): rows ty+16i (i<4), cols tx*8..tx*8+7.
#define GROWS 64
#define XS_STRIDE 132                       // pad: conflict-free scalar A broadcasts
#define GEMM_SMEM ((GROWS * XS_STRIDE + 128 * 128) * 4)
__global__ void k_gemm(const float* __restrict__ x, const float* __restrict__ W, int n) {
    extern __shared__ float smem[];
    float* xs = smem;                        // [64][132]
    float* ws = smem + GROWS * XS_STRIDE;    // [128][128]

    int tid = threadIdx.x;
    int m0 = blockIdx.x * GROWS;

    const float4* W4 = (const float4*)W;
    float4* ws4 = (float4*)ws;
    for (int i = tid; i < 128 * 32; i += 256) ws4[i] = W4[i];

    for (int i = tid; i < GROWS * 32; i += 256) {
        int r = i >> 5;
        int c4 = i & 31;
        float4 v = make_float4(0.f, 0.f, 0.f, 0.f);
        if (m0 + r < n) v = ((const float4*)x)[(size_t)(m0 + r) * 32 + c4];
        *(float4*)&xs[r * XS_STRIDE + c4 * 4] = v;
    }
    __syncthreads();

    int ty = tid >> 4;   // 0..15
    int tx = tid & 15;   // 0..15  -> cols tx*8..tx*8+7
    float acc[4][8];
    #pragma unroll
    for (int i = 0; i < 4; i++)
        #pragma unroll
        for (int j = 0; j < 8; j++) acc[i][j] = 0.f;

    #pragma unroll 8
    for (int k = 0; k < 128; k++) {
        float a[4];
        #pragma unroll
        for (int i = 0; i < 4; i++) a[i] = xs[(ty + 16 * i) * XS_STRIDE + k];
        float4 b0 = *(const float4*)&ws[k * 128 + tx * 8];
        float4 b1 = *(const float4*)&ws[k * 128 + tx * 8 + 4];
        #pragma unroll
        for (int i = 0; i < 4; i++) {
            acc[i][0] = fmaf(a[i], b0.x, acc[i][0]);
            acc[i][1] = fmaf(a[i], b0.y, acc[i][1]);
            acc[i][2] = fmaf(a[i], b0.z, acc[i][2]);
            acc[i][3] = fmaf(a[i], b0.w, acc[i][3]);
            acc[i][4] = fmaf(a[i], b1.x, acc[i][4]);
            acc[i][5] = fmaf(a[i], b1.y, acc[i][5]);
            acc[i][6] = fmaf(a[i], b1.z, acc[i][6]);
            acc[i][7] = fmaf(a[i], b1.w, acc[i][7]);
        }
    }

    #pragma unroll
    for (int i = 0; i < 4; i++) {
        int r = m0 + ty + 16 * i;
        if (r < n) {
            float* hp = &g_h[(size_t)r * CH + tx * 8];
            *(float4*)hp       = make_float4(acc[i][0], acc[i][1], acc[i][2], acc[i][3]);
            *(float4*)(hp + 4) = make_float4(acc[i][4], acc[i][5], acc[i][6], acc[i][7]);
        }
    }
}

// -------- k6: aggregate. One warp per destination node; fused self+bias+relu ----
__global__ void k_agg(const float* __restrict__ bias, float* __restrict__ out, int n) {
    int gt = blockIdx.x * blockDim.x + threadIdx.x;
    int d = gt >> 5;
    int lane = gt & 31;
    if (d >= n) return;

    int p0 = g_rowptr[d];
    int p1 = g_rowptr[d + 1];
    float dd = g_dinv[d];
    const float4* h4 = (const float4*)g_h;

    // self-loop message: h[d] * dinv[d]^2
    float4 acc = h4[(size_t)d * 32 + lane];
    float sw = dd * dd;
    acc.x *= sw; acc.y *= sw; acc.z *= sw; acc.w *= sw;
    float4 acc2 = make_float4(0.f, 0.f, 0.f, 0.f);

    for (int base = p0; base < p1; base += 32) {
        int idx = base + lane;
        int s = 0;
        float w = 0.f;
        if (idx < p1) {
            s = g_esrc[idx];
            w = g_dinv[s] * dd;
        }
        int m = min(32, p1 - base);
        int j = 0;
        for (; j + 2 <= m; j += 2) {
            int   s0 = __shfl_sync(0xffffffffu, s, j);
            float w0 = __shfl_sync(0xffffffffu, w, j);
            int   s1 = __shfl_sync(0xffffffffu, s, j + 1);
            float w1 = __shfl_sync(0xffffffffu, w, j + 1);
            float4 v0 = h4[(size_t)s0 * 32 + lane];
            float4 v1 = h4[(size_t)s1 * 32 + lane];
            acc.x  = fmaf(v0.x, w0, acc.x);  acc.y  = fmaf(v0.y, w0, acc.y);
            acc.z  = fmaf(v0.z, w0, acc.z);  acc.w  = fmaf(v0.w, w0, acc.w);
            acc2.x = fmaf(v1.x, w1, acc2.x); acc2.y = fmaf(v1.y, w1, acc2.y);
            acc2.z = fmaf(v1.z, w1, acc2.z); acc2.w = fmaf(v1.w, w1, acc2.w);
        }
        if (j < m) {
            int   s0 = __shfl_sync(0xffffffffu, s, j);
            float w0 = __shfl_sync(0xffffffffu, w, j);
            float4 v0 = h4[(size_t)s0 * 32 + lane];
            acc.x = fmaf(v0.x, w0, acc.x); acc.y = fmaf(v0.y, w0, acc.y);
            acc.z = fmaf(v0.z, w0, acc.z); acc.w = fmaf(v0.w, w0, acc.w);
        }
    }

    float4 bb = ((const float4*)bias)[lane];
    acc.x = fmaxf(acc.x + acc2.x + bb.x, 0.f);
    acc.y = fmaxf(acc.y + acc2.y + bb.y, 0.f);
    acc.z = fmaxf(acc.z + acc2.z + bb.z, 0.f);
    acc.w = fmaxf(acc.w + acc2.w + bb.w, 0.f);
    ((float4*)out)[(size_t)d * 32 + lane] = acc;
}

extern "C" void kernel_launch(void* const* d_in, const int* in_sizes, int n_in,
                              void* d_out, int out_size) {
    const float* x  = (const float*)d_in[0];
    const int*   ei = (const int*)d_in[1];
    const float* W  = (const float*)d_in[2];
    const float* b  = (const float*)d_in[3];
    float* out = (float*)d_out;

    int n = in_sizes[0] / CH;
    if (n > N_NODES_MAX) n = N_NODES_MAX;
    int E = in_sizes[1] / 2;
    if (E > E_MAX) E = E_MAX;
    const int* src = ei;
    const int* dst = ei + E;

    // Unconditional (idempotent host call; no static guards allowed).
    cudaFuncSetAttribute(k_gemm, cudaFuncAttributeMaxDynamicSharedMemorySize, GEMM_SMEM);

    k_zero<<<(n + 255) / 256, 256>>>(n);
    k_count<<<(E + 255) / 256, 256>>>(dst, E);
    k_scan<<<1, 1024>>>(n, E);
    k_fill<<<(E + 255) / 256, 256>>>(src, dst, E);
    k_gemm<<<(n + GROWS - 1) / GROWS, 256, GEMM_SMEM>>>(x, W, n);
    {
        long long threads = (long long)n * 32;
        int blocks = (int)((threads + 255) / 256);
        k_agg<<<blocks, 256>>>(b, out, n);
    }
}

// round 5
// speedup vs baseline: 1.2489x; 1.2489x over previous
#include <cuda_runtime.h>
#include <cuda_bf16.h>
#include <cstdint>

#define N_NODES_MAX 50000
#define CH 128

// -------- device scratch --------
__device__ float g_h[(size_t)N_NODES_MAX * CH];   // x @ W
__device__ int   g_deg[N_NODES_MAX];
__device__ float g_dinv[N_NODES_MAX];

// -------- k1: deg init (self-loop counts as 1) --------
__global__ void k_init_deg(int n) {
    int i = blockIdx.x * blockDim.x + threadIdx.x;
    if (i < n) g_deg[i] = 1;
}

// -------- k2: histogram over dst --------
__global__ void k_count(const int* __restrict__ dst, int E) {
    int e = blockIdx.x * blockDim.x + threadIdx.x;
    if (e < E) atomicAdd(&g_deg[dst[e]], 1);
}

// -------- k3: dinv = rsqrt(deg) --------
__global__ void k_dinv(int n) {
    int i = blockIdx.x * blockDim.x + threadIdx.x;
    if (i < n) g_dinv[i] = rsqrtf((float)g_deg[i]);
}

// -------- k4: GEMM h = x @ W, fused self-loop epilogue --------
// 64-row tiles, 256 threads. Thread (ty,tx): rows ty+16i (i<4), cols tx*8..tx*8+7.
// Epilogue writes g_h (for scatter gathers) and out = h * dinv^2 (self-loop msg,
// which also initializes the poisoned output buffer).
#define GROWS 64
#define XS_STRIDE 132                       // pad: conflict-free scalar A broadcasts
#define GEMM_SMEM ((GROWS * XS_STRIDE + 128 * 128) * 4)
__global__ void k_gemm(const float* __restrict__ x, const float* __restrict__ W,
                       float* __restrict__ out, int n) {
    extern __shared__ float smem[];
    float* xs = smem;                        // [64][132]
    float* ws = smem + GROWS * XS_STRIDE;    // [128][128]

    int tid = threadIdx.x;
    int m0 = blockIdx.x * GROWS;

    const float4* W4 = (const float4*)W;
    float4* ws4 = (float4*)ws;
    for (int i = tid; i < 128 * 32; i += 256) ws4[i] = W4[i];

    for (int i = tid; i < GROWS * 32; i += 256) {
        int r = i >> 5;
        int c4 = i & 31;
        float4 v = make_float4(0.f, 0.f, 0.f, 0.f);
        if (m0 + r < n) v = ((const float4*)x)[(size_t)(m0 + r) * 32 + c4];
        *(float4*)&xs[r * XS_STRIDE + c4 * 4] = v;
    }
    __syncthreads();

    int ty = tid >> 4;   // 0..15
    int tx = tid & 15;   // 0..15  -> cols tx*8..tx*8+7
    float acc[4][8];
    #pragma unroll
    for (int i = 0; i < 4; i++)
        #pragma unroll
        for (int j = 0; j < 8; j++) acc[i][j] = 0.f;

    #pragma unroll 8
    for (int k = 0; k < 128; k++) {
        float a[4];
        #pragma unroll
        for (int i = 0; i < 4; i++) a[i] = xs[(ty + 16 * i) * XS_STRIDE + k];
        float4 b0 = *(const float4*)&ws[k * 128 + tx * 8];
        float4 b1 = *(const float4*)&ws[k * 128 + tx * 8 + 4];
        #pragma unroll
        for (int i = 0; i < 4; i++) {
            acc[i][0] = fmaf(a[i], b0.x, acc[i][0]);
            acc[i][1] = fmaf(a[i], b0.y, acc[i][1]);
            acc[i][2] = fmaf(a[i], b0.z, acc[i][2]);
            acc[i][3] = fmaf(a[i], b0.w, acc[i][3]);
            acc[i][4] = fmaf(a[i], b1.x, acc[i][4]);
            acc[i][5] = fmaf(a[i], b1.y, acc[i][5]);
            acc[i][6] = fmaf(a[i], b1.z, acc[i][6]);
            acc[i][7] = fmaf(a[i], b1.w, acc[i][7]);
        }
    }

    #pragma unroll
    for (int i = 0; i < 4; i++) {
        int r = m0 + ty + 16 * i;
        if (r < n) {
            float di = g_dinv[r];
            float sw = di * di;
            float4 lo = make_float4(acc[i][0], acc[i][1], acc[i][2], acc[i][3]);
            float4 hi = make_float4(acc[i][4], acc[i][5], acc[i][6], acc[i][7]);
            float* hp = &g_h[(size_t)r * CH + tx * 8];
            *(float4*)hp       = lo;
            *(float4*)(hp + 4) = hi;
            float4 slo = make_float4(lo.x * sw, lo.y * sw, lo.z * sw, lo.w * sw);
            float4 shi = make_float4(hi.x * sw, hi.y * sw, hi.z * sw, hi.w * sw);
            float* op = out + (size_t)r * CH + tx * 8;
            *(float4*)op       = slo;
            *(float4*)(op + 4) = shi;
        }
    }
}

// -------- k5: edge scatter. One warp per edge, red.v4.f32 --------
__global__ void k_scatter(const int* __restrict__ src, const int* __restrict__ dst,
                          float* __restrict__ out, int E) {
    int gt = blockIdx.x * blockDim.x + threadIdx.x;
    int e = gt >> 5;
    int lane = gt & 31;
    if (e >= E) return;
    int s = __ldg(&src[e]);
    int d = __ldg(&dst[e]);
    float norm = g_dinv[s] * g_dinv[d];
    float4 v = __ldg(((const float4*)&g_h[(size_t)s * CH]) + lane);
    v.x *= norm; v.y *= norm; v.z *= norm; v.w *= norm;
    float* p = out + (size_t)d * CH + lane * 4;
    asm volatile("red.global.add.v4.f32 [%0], {%1, %2, %3, %4};"
                 :: "l"(p), "f"(v.x), "f"(v.y), "f"(v.z), "f"(v.w)
                 : "memory");
}

// -------- k6: out = relu(out + b) --------
__global__ void k_bias_relu(float* __restrict__ out, const float* __restrict__ b, int n) {
    int i = blockIdx.x * blockDim.x + threadIdx.x;  // over n*32 float4s
    if (i >= n * 32) return;
    float4 v = ((float4*)out)[i];
    float4 bb = ((const float4*)b)[i & 31];
    v.x = fmaxf(v.x + bb.x, 0.f);
    v.y = fmaxf(v.y + bb.y, 0.f);
    v.z = fmaxf(v.z + bb.z, 0.f);
    v.w = fmaxf(v.w + bb.w, 0.f);
    ((float4*)out)[i] = v;
}

extern "C" void kernel_launch(void* const* d_in, const int* in_sizes, int n_in,
                              void* d_out, int out_size) {
    const float* x  = (const float*)d_in[0];
    const int*   ei = (const int*)d_in[1];
    const float* W  = (const float*)d_in[2];
    const float* b  = (const float*)d_in[3];
    float* out = (float*)d_out;

    int n = in_sizes[0] / CH;
    if (n > N_NODES_MAX) n = N_NODES_MAX;
    int E = in_sizes[1] / 2;
    const int* src = ei;
    const int* dst = ei + E;

    // Unconditional (idempotent host call; no static guards allowed).
    cudaFuncSetAttribute(k_gemm, cudaFuncAttributeMaxDynamicSharedMemorySize, GEMM_SMEM);

    k_init_deg<<<(n + 255) / 256, 256>>>(n);
    k_count<<<(E + 255) / 256, 256>>>(dst, E);
    k_dinv<<<(n + 255) / 256, 256>>>(n);
    k_gemm<<<(n + GROWS - 1) / GROWS, 256, GEMM_SMEM>>>(x, W, out, n);
    {
        long long threads = (long long)E * 32;
        int blocks = (int)((threads + 255) / 256);
        k_scatter<<<blocks, 256>>>(src, dst, out, E);
    }
    k_bias_relu<<<(n * 32 + 255) / 256, 256>>>(out, b, n);
}

// round 6
// speedup vs baseline: 1.6442x; 1.3165x over previous
#include <cuda_runtime.h>
#include <cuda_bf16.h>
#include <cstdint>

#define N_NODES_MAX 50000
#define CH 128

// -------- device scratch --------
__device__ float g_h[(size_t)N_NODES_MAX * CH];   // x @ W
__device__ int   g_deg[N_NODES_MAX];
__device__ float g_dinv[N_NODES_MAX];
__device__ __nv_bfloat16 g_wt_hi[CH * CH];        // W^T, bf16 hi part: [n][k]
__device__ __nv_bfloat16 g_wt_lo[CH * CH];        // W^T, bf16 lo part

// -------- k1: deg init (self-loop counts as 1) --------
__global__ void k_init_deg(int n) {
    int i = blockIdx.x * blockDim.x + threadIdx.x;
    if (i < n) g_deg[i] = 1;
}

// -------- k2: histogram over dst --------
__global__ void k_count(const int* __restrict__ dst, int E) {
    int e = blockIdx.x * blockDim.x + threadIdx.x;
    if (e < E) atomicAdd(&g_deg[dst[e]], 1);
}

// -------- k3: dinv = rsqrt(deg) --------
__global__ void k_dinv(int n) {
    int i = blockIdx.x * blockDim.x + threadIdx.x;
    if (i < n) g_dinv[i] = rsqrtf((float)g_deg[i]);
}

// -------- k4: split+transpose W into bf16 hi/lo --------
__global__ void k_wconv(const float* __restrict__ W) {
    int i = blockIdx.x * blockDim.x + threadIdx.x;   // over 16384
    if (i >= CH * CH) return;
    int k = i >> 7;          // row of W
    int nn = i & 127;        // col of W
    float w = W[i];
    __nv_bfloat16 hi = __float2bfloat16(w);
    float r = w - __bfloat162float(hi);
    g_wt_hi[nn * CH + k] = hi;
    g_wt_lo[nn * CH + k] = __float2bfloat16(r);
}

// -------- k5: GEMM h = x @ W via bf16-split mma.sync, fused self-loop epilogue --
// CTA: 64 rows x 128 cols; 8 warps; warp tile m16 x n64 (warp_m = wid&3, warp_n = wid>>2).
// smem strides padded to 68 b32 words/row -> conflict-free fragment LDS.
#define M_BLK 64
#define SROW 68   // b32 words per smem row (holds 64 words = 128 bf16, +4 pad)
#define GEMM_SMEM ((M_BLK * SROW * 2 + CH * SROW * 2) * 4)

__device__ __forceinline__ void mma_bf16(float& d0, float& d1, float& d2, float& d3,
                                         uint32_t a0, uint32_t a1, uint32_t a2, uint32_t a3,
                                         uint32_t b0, uint32_t b1) {
    asm volatile("mma.sync.aligned.m16n8k16.row.col.f32.bf16.bf16.f32 "
                 "{%0,%1,%2,%3}, {%4,%5,%6,%7}, {%8,%9}, {%0,%1,%2,%3};"
                 : "+f"(d0), "+f"(d1), "+f"(d2), "+f"(d3)
                 : "r"(a0), "r"(a1), "r"(a2), "r"(a3), "r"(b0), "r"(b1));
}

__global__ void k_gemm(const float* __restrict__ x, float* __restrict__ out, int n) {
    extern __shared__ uint32_t smem[];
    uint32_t* xs_hi = smem;                       // [64][68] words
    uint32_t* xs_lo = xs_hi + M_BLK * SROW;
    uint32_t* wt_hi = xs_lo + M_BLK * SROW;       // [128][68] words
    uint32_t* wt_lo = wt_hi + CH * SROW;

    int tid = threadIdx.x;
    int m0 = blockIdx.x * M_BLK;

    // stage W^T hi/lo (bf16, 16 int4 per 128-col row)
    {
        const int4* src_hi = (const int4*)g_wt_hi;
        const int4* src_lo = (const int4*)g_wt_lo;
        for (int i = tid; i < CH * 16; i += 256) {
            int r = i >> 4, v = i & 15;
            *(int4*)&wt_hi[r * SROW + v * 4] = src_hi[i];
            *(int4*)&wt_lo[r * SROW + v * 4] = src_lo[i];
        }
    }
    // stage x tile: load float4, split to bf16 hi/lo
    for (int i = tid; i < M_BLK * 32; i += 256) {
        int r = i >> 5, c4 = i & 31;      // cols c4*4..c4*4+3
        float4 v = make_float4(0.f, 0.f, 0.f, 0.f);
        if (m0 + r < n) v = ((const float4*)x)[(size_t)(m0 + r) * 32 + c4];
        __nv_bfloat162 h0 = make_bfloat162(__float2bfloat16(v.x), __float2bfloat16(v.y));
        __nv_bfloat162 h1 = make_bfloat162(__float2bfloat16(v.z), __float2bfloat16(v.w));
        __nv_bfloat162 l0 = make_bfloat162(
            __float2bfloat16(v.x - __bfloat162float(h0.x)),
            __float2bfloat16(v.y - __bfloat162float(h0.y)));
        __nv_bfloat162 l1 = make_bfloat162(
            __float2bfloat16(v.z - __bfloat162float(h1.x)),
            __float2bfloat16(v.w - __bfloat162float(h1.y)));
        uint32_t* ph = &xs_hi[r * SROW + c4 * 2];
        uint32_t* pl = &xs_lo[r * SROW + c4 * 2];
        ph[0] = *(uint32_t*)&h0; ph[1] = *(uint32_t*)&h1;
        pl[0] = *(uint32_t*)&l0; pl[1] = *(uint32_t*)&l1;
    }
    __syncthreads();

    int lane = tid & 31;
    int wid = tid >> 5;
    int warp_m = wid & 3;          // row group: 16 rows
    int warp_n = wid >> 2;         // col group: 64 cols
    int r0 = warp_m * 16 + (lane >> 2);        // local row for fragments
    int qlane = lane & 3;

    float acc[8][4];
    #pragma unroll
    for (int t = 0; t < 8; t++)
        #pragma unroll
        for (int j = 0; j < 4; j++) acc[t][j] = 0.f;

    #pragma unroll
    for (int k0 = 0; k0 < 8; k0++) {
        int q = k0 * 8 + qlane;
        uint32_t ah0 = xs_hi[r0 * SROW + q];
        uint32_t ah1 = xs_hi[(r0 + 8) * SROW + q];
        uint32_t ah2 = xs_hi[r0 * SROW + q + 4];
        uint32_t ah3 = xs_hi[(r0 + 8) * SROW + q + 4];
        uint32_t al0 = xs_lo[r0 * SROW + q];
        uint32_t al1 = xs_lo[(r0 + 8) * SROW + q];
        uint32_t al2 = xs_lo[r0 * SROW + q + 4];
        uint32_t al3 = xs_lo[(r0 + 8) * SROW + q + 4];
        #pragma unroll
        for (int nt = 0; nt < 8; nt++) {
            int nn = warp_n * 64 + nt * 8 + (lane >> 2);
            uint32_t bh0 = wt_hi[nn * SROW + q];
            uint32_t bh1 = wt_hi[nn * SROW + q + 4];
            uint32_t bl0 = wt_lo[nn * SROW + q];
            uint32_t bl1 = wt_lo[nn * SROW + q + 4];
            mma_bf16(acc[nt][0], acc[nt][1], acc[nt][2], acc[nt][3],
                     ah0, ah1, ah2, ah3, bh0, bh1);
            mma_bf16(acc[nt][0], acc[nt][1], acc[nt][2], acc[nt][3],
                     ah0, ah1, ah2, ah3, bl0, bl1);
            mma_bf16(acc[nt][0], acc[nt][1], acc[nt][2], acc[nt][3],
                     al0, al1, al2, al3, bh0, bh1);
        }
    }

    // epilogue: rows gr, gr+8; cols warp_n*64 + nt*8 + 2*(lane&3)
    int gr = m0 + r0;
    bool ok0 = (gr < n), ok1 = (gr + 8 < n);
    float sw0 = 0.f, sw1 = 0.f;
    if (ok0) { float d = g_dinv[gr];     sw0 = d * d; }
    if (ok1) { float d = g_dinv[gr + 8]; sw1 = d * d; }
    #pragma unroll
    for (int nt = 0; nt < 8; nt++) {
        int col = warp_n * 64 + nt * 8 + 2 * qlane;
        if (ok0) {
            float2 v = make_float2(acc[nt][0], acc[nt][1]);
            *(float2*)&g_h[(size_t)gr * CH + col] = v;
            *(float2*)&out[(size_t)gr * CH + col] = make_float2(v.x * sw0, v.y * sw0);
        }
        if (ok1) {
            float2 v = make_float2(acc[nt][2], acc[nt][3]);
            *(float2*)&g_h[(size_t)(gr + 8) * CH + col] = v;
            *(float2*)&out[(size_t)(gr + 8) * CH + col] = make_float2(v.x * sw1, v.y * sw1);
        }
    }
}

// -------- k6: edge scatter. One warp per edge, red.v4.f32 --------
__global__ void k_scatter(const int* __restrict__ src, const int* __restrict__ dst,
                          float* __restrict__ out, int E) {
    int gt = blockIdx.x * blockDim.x + threadIdx.x;
    int e = gt >> 5;
    int lane = gt & 31;
    if (e >= E) return;
    int s = __ldg(&src[e]);
    int d = __ldg(&dst[e]);
    float norm = g_dinv[s] * g_dinv[d];
    float4 v = __ldg(((const float4*)&g_h[(size_t)s * CH]) + lane);
    v.x *= norm; v.y *= norm; v.z *= norm; v.w *= norm;
    float* p = out + (size_t)d * CH + lane * 4;
    asm volatile("red.global.add.v4.f32 [%0], {%1, %2, %3, %4};"
                 :: "l"(p), "f"(v.x), "f"(v.y), "f"(v.z), "f"(v.w)
                 : "memory");
}

// -------- k7: out = relu(out + b) --------
__global__ void k_bias_relu(float* __restrict__ out, const float* __restrict__ b, int n) {
    int i = blockIdx.x * blockDim.x + threadIdx.x;  // over n*32 float4s
    if (i >= n * 32) return;
    float4 v = ((float4*)out)[i];
    float4 bb = ((const float4*)b)[i & 31];
    v.x = fmaxf(v.x + bb.x, 0.f);
    v.y = fmaxf(v.y + bb.y, 0.f);
    v.z = fmaxf(v.z + bb.z, 0.f);
    v.w = fmaxf(v.w + bb.w, 0.f);
    ((float4*)out)[i] = v;
}

extern "C" void kernel_launch(void* const* d_in, const int* in_sizes, int n_in,
                              void* d_out, int out_size) {
    const float* x  = (const float*)d_in[0];
    const int*   ei = (const int*)d_in[1];
    const float* W  = (const float*)d_in[2];
    const float* b  = (const float*)d_in[3];
    float* out = (float*)d_out;

    int n = in_sizes[0] / CH;
    if (n > N_NODES_MAX) n = N_NODES_MAX;
    int E = in_sizes[1] / 2;
    const int* src = ei;
    const int* dst = ei + E;

    cudaFuncSetAttribute(k_gemm, cudaFuncAttributeMaxDynamicSharedMemorySize, GEMM_SMEM);

    k_init_deg<<<(n + 255) / 256, 256>>>(n);
    k_count<<<(E + 255) / 256, 256>>>(dst, E);
    k_dinv<<<(n + 255) / 256, 256>>>(n);
    k_wconv<<<(CH * CH + 255) / 256, 256>>>(W);
    k_gemm<<<(n + M_BLK - 1) / M_BLK, 256, GEMM_SMEM>>>(x, out, n);
    {
        long long threads = (long long)E * 32;
        int blocks = (int)((threads + 255) / 256);
        k_scatter<<<blocks, 256>>>(src, dst, out, E);
    }
    k_bias_relu<<<(n * 32 + 255) / 256, 256>>>(out, b, n);
}

// round 8
// speedup vs baseline: 1.7341x; 1.0547x over previous
#include <cuda_runtime.h>
#include <cuda_bf16.h>
#include <cstdint>

#define N_NODES_MAX 50000
#define CH 128

// -------- device scratch --------
__device__ float g_h[(size_t)N_NODES_MAX * CH];   // x @ W
__device__ int   g_deg[N_NODES_MAX];              // zero-init; invariant: zero on entry & exit
__device__ float g_dinv[N_NODES_MAX];
__device__ __nv_bfloat16 g_wt_hi[CH * CH];        // W^T bf16 hi: [n][k]
__device__ __nv_bfloat16 g_wt_lo[CH * CH];        // W^T bf16 lo

// -------- k1: fused histogram(dst) + W split/transpose --------
// Blocks [0, CB): degree count.  Blocks [CB, CB+WB): wconv.
__global__ void k_pre(const int* __restrict__ dst, int E,
                      const float* __restrict__ W, int CB) {
    int b = blockIdx.x;
    if (b < CB) {
        int e = b * 256 + threadIdx.x;
        if (e < E) atomicAdd(&g_deg[dst[e]], 1);   // result unused -> RED
    } else {
        int i = (b - CB) * 256 + threadIdx.x;
        if (i < CH * CH) {
            int k = i >> 7, nn = i & 127;
            float w = W[i];
            __nv_bfloat16 hi = __float2bfloat16(w);
            g_wt_hi[nn * CH + k] = hi;
            g_wt_lo[nn * CH + k] = __float2bfloat16(w - __bfloat162float(hi));
        }
    }
}

// -------- k2: GEMM h = x @ W via bf16-split mma + ldmatrix; fused dinv + self-loop
#define M_BLK 64
#define SROW 68   // b32 words per smem row (64 data words + 4 pad) -> conflict-free LDSM
#define GEMM_SMEM ((M_BLK * SROW * 2 + CH * SROW * 2 + 64) * 4)

__device__ __forceinline__ void ldsm4(uint32_t& r0, uint32_t& r1, uint32_t& r2, uint32_t& r3,
                                      uint32_t addr) {
    asm volatile("ldmatrix.sync.aligned.m8n8.x4.shared.b16 {%0,%1,%2,%3}, [%4];"
                 : "=r"(r0), "=r"(r1), "=r"(r2), "=r"(r3) : "r"(addr));
}
__device__ __forceinline__ void mma_bf16(float& d0, float& d1, float& d2, float& d3,
                                         uint32_t a0, uint32_t a1, uint32_t a2, uint32_t a3,
                                         uint32_t b0, uint32_t b1) {
    asm volatile("mma.sync.aligned.m16n8k16.row.col.f32.bf16.bf16.f32 "
                 "{%0,%1,%2,%3}, {%4,%5,%6,%7}, {%8,%9}, {%0,%1,%2,%3};"
                 : "+f"(d0), "+f"(d1), "+f"(d2), "+f"(d3)
                 : "r"(a0), "r"(a1), "r"(a2), "r"(a3), "r"(b0), "r"(b1));
}

__global__ void k_gemm(const float* __restrict__ x, float* __restrict__ out, int n) {
    extern __shared__ uint32_t smem[];
    uint32_t* xs_hi = smem;                       // [64][68] words
    uint32_t* xs_lo = xs_hi + M_BLK * SROW;
    uint32_t* wt_hi = xs_lo + M_BLK * SROW;       // [128][68] words
    uint32_t* wt_lo = wt_hi + CH * SROW;
    float*    sdinv = (float*)(wt_lo + CH * SROW);  // [64]

    int tid = threadIdx.x;
    int m0 = blockIdx.x * M_BLK;

    // dinv for this tile (also resets g_deg to keep zero-invariant across replays)
    if (tid < M_BLK) {
        int r = m0 + tid;
        float d = 0.f;
        if (r < n) {
            int c = g_deg[r];
            d = rsqrtf((float)(c + 1));
            g_dinv[r] = d;
            g_deg[r] = 0;
        }
        sdinv[tid] = d;
    }

    // stage W^T hi/lo
    {
        const int4* src_hi = (const int4*)g_wt_hi;
        const int4* src_lo = (const int4*)g_wt_lo;
        for (int i = tid; i < CH * 16; i += 256) {
            int r = i >> 4, v = i & 15;
            *(int4*)&wt_hi[r * SROW + v * 4] = src_hi[i];
            *(int4*)&wt_lo[r * SROW + v * 4] = src_lo[i];
        }
    }
    // stage x tile: fp32 -> bf16 hi/lo split
    for (int i = tid; i < M_BLK * 32; i += 256) {
        int r = i >> 5, c4 = i & 31;
        float4 v = make_float4(0.f, 0.f, 0.f, 0.f);
        if (m0 + r < n) v = ((const float4*)x)[(size_t)(m0 + r) * 32 + c4];
        __nv_bfloat162 h0 = make_bfloat162(__float2bfloat16(v.x), __float2bfloat16(v.y));
        __nv_bfloat162 h1 = make_bfloat162(__float2bfloat16(v.z), __float2bfloat16(v.w));
        __nv_bfloat162 l0 = make_bfloat162(
            __float2bfloat16(v.x - __bfloat162float(h0.x)),
            __float2bfloat16(v.y - __bfloat162float(h0.y)));
        __nv_bfloat162 l1 = make_bfloat162(
            __float2bfloat16(v.z - __bfloat162float(h1.x)),
            __float2bfloat16(v.w - __bfloat162float(h1.y)));
        uint32_t* ph = &xs_hi[r * SROW + c4 * 2];
        uint32_t* pl = &xs_lo[r * SROW + c4 * 2];
        ph[0] = *(uint32_t*)&h0; ph[1] = *(uint32_t*)&h1;
        pl[0] = *(uint32_t*)&l0; pl[1] = *(uint32_t*)&l1;
    }
    __syncthreads();

    int lane = tid & 31;
    int wid = tid >> 5;
    int warp_m = wid & 3;          // 16-row group
    int warp_n = wid >> 2;         // 64-col group
    int qlane = lane & 3;

    uint32_t smem_u32 = (uint32_t)__cvta_generic_to_shared(smem);
    // A LDSM addr: row = warp_m*16 + (lane&15); +16B for lanes 16-31 (k+8 tiles)
    uint32_t a_addr = smem_u32 +
        ((warp_m * 16 + (lane & 15)) * SROW + (lane >> 4) * 4) * 4;
    const uint32_t A_LO_D = M_BLK * SROW * 4;
    // B LDSM addr (x4 fetches two n8-groups): n = warp_n*64 + (lane&7) + (lane>=16)*8
    //   word +4 for lanes 8-15 / 24-31 (k+8 tiles)
    uint32_t b_addr = smem_u32 + (2 * M_BLK * SROW) * 4 +
        ((warp_n * 64 + (lane & 7) + ((lane >> 4) & 1) * 8) * SROW +
         ((lane >> 3) & 1) * 4) * 4;
    const uint32_t B_LO_D = CH * SROW * 4;
    const uint32_t B_PAIR_D = 16 * SROW * 4;

    float acc[8][4];
    #pragma unroll
    for (int t = 0; t < 8; t++)
        #pragma unroll
        for (int j = 0; j < 4; j++) acc[t][j] = 0.f;

    #pragma unroll
    for (int k0 = 0; k0 < 8; k0++) {
        uint32_t ka = a_addr + k0 * 32;
        uint32_t ah0, ah1, ah2, ah3, al0, al1, al2, al3;
        ldsm4(ah0, ah1, ah2, ah3, ka);
        ldsm4(al0, al1, al2, al3, ka + A_LO_D);
        #pragma unroll
        for (int pr = 0; pr < 4; pr++) {
            uint32_t kb = b_addr + pr * B_PAIR_D + k0 * 32;
            uint32_t bh0, bh1, bh2, bh3, bl0, bl1, bl2, bl3;
            ldsm4(bh0, bh1, bh2, bh3, kb);
            ldsm4(bl0, bl1, bl2, bl3, kb + B_LO_D);
            int nA = pr * 2, nB = pr * 2 + 1;
            mma_bf16(acc[nA][0], acc[nA][1], acc[nA][2], acc[nA][3],
                     ah0, ah1, ah2, ah3, bh0, bh1);
            mma_bf16(acc[nA][0], acc[nA][1], acc[nA][2], acc[nA][3],
                     ah0, ah1, ah2, ah3, bl0, bl1);
            mma_bf16(acc[nA][0], acc[nA][1], acc[nA][2], acc[nA][3],
                     al0, al1, al2, al3, bh0, bh1);
            mma_bf16(acc[nB][0], acc[nB][1], acc[nB][2], acc[nB][3],
                     ah0, ah1, ah2, ah3, bh2, bh3);
            mma_bf16(acc[nB][0], acc[nB][1], acc[nB][2], acc[nB][3],
                     ah0, ah1, ah2, ah3, bl2, bl3);
            mma_bf16(acc[nB][0], acc[nB][1], acc[nB][2], acc[nB][3],
                     al0, al1, al2, al3, bh2, bh3);
        }
    }

    // epilogue: rows r0loc, r0loc+8; cols warp_n*64 + nt*8 + 2*qlane
    int r0loc = warp_m * 16 + (lane >> 2);
    int gr = m0 + r0loc;
    bool ok0 = (gr < n), ok1 = (gr + 8 < n);
    float sw0 = sdinv[r0loc];     sw0 *= sw0;
    float sw1 = sdinv[r0loc + 8]; sw1 *= sw1;
    #pragma unroll
    for (int nt = 0; nt < 8; nt++) {
        int col = warp_n * 64 + nt * 8 + 2 * qlane;
        if (ok0) {
            float2 v = make_float2(acc[nt][0], acc[nt][1]);
            *(float2*)&g_h[(size_t)gr * CH + col] = v;
            *(float2*)&out[(size_t)gr * CH + col] = make_float2(v.x * sw0, v.y * sw0);
        }
        if (ok1) {
            float2 v = make_float2(acc[nt][2], acc[nt][3]);
            *(float2*)&g_h[(size_t)(gr + 8) * CH + col] = v;
            *(float2*)&out[(size_t)(gr + 8) * CH + col] = make_float2(v.x * sw1, v.y * sw1);
        }
    }
}

// -------- k3: edge scatter. One warp per edge, red.v4.f32 --------
__global__ void k_scatter(const int* __restrict__ src, const int* __restrict__ dst,
                          float* __restrict__ out, int E) {
    int gt = blockIdx.x * blockDim.x + threadIdx.x;
    int e = gt >> 5;
    int lane = gt & 31;
    if (e >= E) return;
    int s = __ldg(&src[e]);
    int d = __ldg(&dst[e]);
    float norm = g_dinv[s] * g_dinv[d];
    float4 v = __ldg(((const float4*)&g_h[(size_t)s * CH]) + lane);
    v.x *= norm; v.y *= norm; v.z *= norm; v.w *= norm;
    float* p = out + (size_t)d * CH + lane * 4;
    asm volatile("red.global.add.v4.f32 [%0], {%1, %2, %3, %4};"
                 :: "l"(p), "f"(v.x), "f"(v.y), "f"(v.z), "f"(v.w)
                 : "memory");
}

// -------- k4: out = relu(out + b) --------
__global__ void k_bias_relu(float* __restrict__ out, const float* __restrict__ b, int n) {
    int i = blockIdx.x * blockDim.x + threadIdx.x;
    if (i >= n * 32) return;
    float4 v = ((float4*)out)[i];
    float4 bb = ((const float4*)b)[i & 31];
    v.x = fmaxf(v.x + bb.x, 0.f);
    v.y = fmaxf(v.y + bb.y, 0.f);
    v.z = fmaxf(v.z + bb.z, 0.f);
    v.w = fmaxf(v.w + bb.w, 0.f);
    ((float4*)out)[i] = v;
}

extern "C" void kernel_launch(void* const* d_in, const int* in_sizes, int n_in,
                              void* d_out, int out_size) {
    const float* x  = (const float*)d_in[0];
    const int*   ei = (const int*)d_in[1];
    const float* W  = (const float*)d_in[2];
    const float* b  = (const float*)d_in[3];
    float* out = (float*)d_out;

    int n = in_sizes[0] / CH;
    if (n > N_NODES_MAX) n = N_NODES_MAX;
    int E = in_sizes[1] / 2;
    const int* src = ei;
    const int* dst = ei + E;

    cudaFuncSetAttribute(k_gemm, cudaFuncAttributeMaxDynamicSharedMemorySize, GEMM_SMEM);

    int CB = (E + 255) / 256;
    int WB = (CH * CH + 255) / 256;
    k_pre<<<CB + WB, 256>>>(dst, E, W, CB);
    k_gemm<<<(n + M_BLK - 1) / M_BLK, 256, GEMM_SMEM>>>(x, out, n);
    {
        long long threads = (long long)E * 32;
        int blocks = (int)((threads + 255) / 256);
        k_scatter<<<blocks, 256>>>(src, dst, out, E);
    }
    k_bias_relu<<<(n * 32 + 255) / 256, 256>>>(out, b, n);
}